// round 12
// baseline (speedup 1.0000x reference)
#include <cuda_runtime.h>
#include <math.h>
#include <stdint.h>

#define VOCAB    128000
#define NSEQ     256
#define TOPK     50
#define NTHREADS 1024
#define NBINS    2048          // slow path only (11-bit orderable)
#define CAP      512           // candidate capacity == sort size
#define NV4      (VOCAB / 4)
#define THX      2.85f         // raw-logit prefilter
#define THY      3.5625f       // = THX/0.8 : upper bound on y for filtered elements
#define HSIZE    4096
#define HMASK    4095
#define HEMPTY   0xFFFFFFFFu

// ---- Pure-write zero-fill of the probs region (separate kernel: no R/W interleave) ----
__global__ void k_zero(float4* __restrict__ p, int n4) {
  int i = blockIdx.x * blockDim.x + threadIdx.x;
  int stride = gridDim.x * blockDim.x;
  const float4 z = make_float4(0.f, 0.f, 0.f, 0.f);
  for (; i < n4; i += stride) __stcs(&p[i], z);
}

// smem hash slot: [id:17][eos:1][prompt:1][cnt:13]
__device__ __forceinline__ void hinsert(unsigned* h, unsigned id, unsigned addv, unsigned orv) {
  unsigned slot = (id * 2654435761u) >> 20;
  unsigned tag = id << 15;
  for (;;) {
    unsigned cur = h[slot];
    if (cur == HEMPTY) {
      unsigned prev = atomicCAS(&h[slot], HEMPTY, tag);
      cur = (prev == HEMPTY) ? tag : prev;
    }
    if ((cur >> 15) == id) {
      if (orv)  atomicOr(&h[slot], orv);
      if (addv) atomicAdd(&h[slot], addv);
      return;
    }
    slot = (slot + 1) & HMASK;
  }
}
__device__ __forceinline__ unsigned hlookup(const unsigned* h, unsigned id) {
  unsigned slot = (id * 2654435761u) >> 20;
  for (;;) {
    unsigned cur = h[slot];
    if (cur == HEMPTY) return 0u;
    if ((cur >> 15) == id) return cur;
    slot = (slot + 1) & HMASK;
  }
}

// Bit-faithful to the reference float path: every op rounded separately (no FFMA).
__device__ __forceinline__ float adjust_logit(float x, unsigned cur) {
  if (cur & (1u << 14)) return -INFINITY;                  // eos mask
  unsigned cnt = cur & 0x1FFFu;
  bool penal = (cur & (1u << 13)) || (cnt != 0);           // prompt|output mask
  float rep = penal ? 1.1f : 1.0f;
  float y = (x > 0.0f) ? __fdiv_rn(x, rep) : __fmul_rn(x, rep);
  y = __fsub_rn(y, __fmul_rn(0.1f, (float)cnt));           // frequency
  if (cnt > 0) y = __fsub_rn(y, 0.2f);                     // presence
  y = __fdiv_rn(y, 0.8f);                                  // temperature
  return y;
}

__device__ __forceinline__ unsigned orderable(float f) {
  unsigned u = __float_as_uint(f);
  return (u & 0x80000000u) ? ~u : (u | 0x80000000u);
}
__device__ __forceinline__ float inv_orderable(unsigned o) {
  return __uint_as_float((o & 0x80000000u) ? (o ^ 0x80000000u) : ~o);
}

// JAX threefry2x32, partitionable: bits = x0 ^ x1 of threefry(key=(0,1), counter=(0, n))
__device__ __forceinline__ float gumbel_at(long long n) {
  unsigned c0 = (unsigned)((unsigned long long)n >> 32);
  unsigned c1 = (unsigned)n;
  const unsigned ks0 = 0u, ks1 = 1u, ks2 = 0x1BD11BDBu;
  unsigned x0 = c0 + ks0, x1 = c1 + ks1;
#define TF_RND(r) { x0 += x1; x1 = (x1 << (r)) | (x1 >> (32 - (r))); x1 ^= x0; }
  TF_RND(13) TF_RND(15) TF_RND(26) TF_RND(6)  x0 += ks1; x1 += ks2 + 1u;
  TF_RND(17) TF_RND(29) TF_RND(16) TF_RND(24) x0 += ks2; x1 += ks0 + 2u;
  TF_RND(13) TF_RND(15) TF_RND(26) TF_RND(6)  x0 += ks0; x1 += ks1 + 3u;
  TF_RND(17) TF_RND(29) TF_RND(16) TF_RND(24) x0 += ks1; x1 += ks2 + 4u;
  TF_RND(13) TF_RND(15) TF_RND(26) TF_RND(6)  x0 += ks2; x1 += ks0 + 5u;
#undef TF_RND
  unsigned bits = x0 ^ x1;
  float f = __uint_as_float((bits >> 9) | 0x3f800000u) - 1.0f;
  float u = fmaxf(__uint_as_float(0x00800000u), f);
  return -logf(-logf(u));
}

#define BAR512() asm volatile("bar.sync 1, 512;" ::: "memory")

// Descending bitonic sort of 512 u64 keys, one per thread (tid<512 call this).
__device__ __forceinline__ unsigned long long sort512(
    unsigned long long e, unsigned long long* bufA, unsigned long long* bufB, int tid) {
  int phase = 0;
#pragma unroll
  for (int k = 2; k <= 512; k <<= 1) {
#pragma unroll
    for (int j = k >> 1; j > 0; j >>= 1) {
      unsigned long long o;
      if (j < 32) {
        o = __shfl_xor_sync(0xffffffffu, e, j);
      } else {
        unsigned long long* buf = (phase & 1) ? bufB : bufA;
        buf[tid] = e;
        BAR512();
        o = buf[tid ^ j];
        phase ^= 1;
      }
      bool dirAsc = ((tid & k) != 0);       // final pass: all descending
      bool lower  = ((tid & j) == 0);
      bool takeMin = (dirAsc == lower);
      if (takeMin ? (o < e) : (o > e)) e = o;
    }
  }
  BAR512();
  bufA[tid] = e;
  return e;
}

__global__ __launch_bounds__(NTHREADS, 2)
void k_main(const float* __restrict__ logits,
            const int* __restrict__ prompt, int np,
            const int* __restrict__ outtok, int no,
            const int* __restrict__ eos, int ne,
            float* __restrict__ out,
            int prob_off, int tok_off, int tok_int) {
  __shared__ unsigned s_hash[HSIZE];                     // 16 KB
  __shared__ __align__(16) unsigned long long bufA[CAP]; // 4 KB
  __shared__ __align__(16) unsigned long long u64mem[1024]; // 8 KB union
  __shared__ float se[CAP];                              // 2 KB
  __shared__ unsigned partial[NTHREADS];                 // 4 KB (slow path)
  __shared__ unsigned s_cnt;
  __shared__ int s_g, s_bstar, s_J, s_ok, s_n;
  __shared__ float s_Z;

  unsigned long long* bufB = u64mem;
  float* sval = (float*)(u64mem + 512);
  int*   sidx = (int*)((char*)(u64mem + 512) + 2048);
  unsigned* hist = (unsigned*)u64mem;

  const int s = blockIdx.x;
  const int tid = threadIdx.x;

  // ---- Per-CTA penalty hash build ----
  for (int i = tid; i < HSIZE; i += NTHREADS) s_hash[i] = HEMPTY;
  if (tid == 0) { s_cnt = 0u; s_g = 0; }
  __syncthreads();
  for (int i = tid; i < np; i += NTHREADS) hinsert(s_hash, (unsigned)prompt[i], 0u, 1u << 13);
  for (int i = tid; i < no; i += NTHREADS) hinsert(s_hash, (unsigned)outtok[i], 1u, 0u);
  for (int i = tid; i < ne; i += NTHREADS) hinsert(s_hash, (unsigned)eos[i], 0u, 1u << 14);
  __syncthreads();

  const float4* row4 = (const float4*)(logits + (size_t)s * VOCAB);

  // ---- Pure-read streaming pass: prefiltered candidate collection (no stores) ----
#pragma unroll 8
  for (int c = tid; c < NV4; c += NTHREADS) {
    float4 t = __ldcs(&row4[c]);
    float mx = fmaxf(fmaxf(t.x, t.y), fmaxf(t.z, t.w));
    if (mx > THX) {
      int vb = c * 4;
      float xs4[4] = {t.x, t.y, t.z, t.w};
#pragma unroll
      for (int q = 0; q < 4; q++) {
        if (xs4[q] > THX) {
          unsigned cur = hlookup(s_hash, (unsigned)(vb + q));
          unsigned o = orderable(adjust_logit(xs4[q], cur));
          unsigned p = atomicAdd(&s_cnt, 1u);
          if (p < CAP) bufA[p] = ((unsigned long long)o << 32) | (unsigned)(vb + q);
        }
      }
    }
  }
  __syncthreads();

  int n = (int)s_cnt;
  bool okn = (n >= TOPK && n <= CAP);
  if (okn) {
    if (tid < CAP) {
      unsigned long long e = (tid < n) ? bufA[tid] : 0ull;
      sort512(e, bufA, bufB, tid);
    }
    __syncthreads();
    if (tid == 0) {
      float v50 = inv_orderable((unsigned)(bufA[TOPK - 1] >> 32));
      s_ok = (v50 > THY) ? 1 : 0;     // candidate set provably covers top-k + ties
      s_n = n;
    }
  } else {
    if (tid == 0) s_ok = 0;
  }
  __syncthreads();

  // ---- Guarded slow path (histogram select over full vocab; bit-identical math) ----
  if (!s_ok) {
    for (int i = tid; i < NBINS; i += NTHREADS) hist[i] = 0u;
    if (tid == 0) s_cnt = 0u;
    __syncthreads();
    for (int c = tid; c < NV4; c += NTHREADS) {
      float4 t = row4[c];
      int vb = c * 4;
      float xs4[4] = {t.x, t.y, t.z, t.w};
#pragma unroll
      for (int q = 0; q < 4; q++) {
        unsigned cur = hlookup(s_hash, (unsigned)(vb + q));
        atomicAdd(&hist[orderable(adjust_logit(xs4[q], cur)) >> 21], 1u);
      }
    }
    __syncthreads();
    unsigned ps = hist[2 * tid] + hist[2 * tid + 1];
    partial[tid] = ps;
    __syncthreads();
    for (int off = 1; off < NTHREADS; off <<= 1) {
      unsigned a = (tid + off < NTHREADS) ? partial[tid + off] : 0u;
      __syncthreads();
      partial[tid] += a;
      __syncthreads();
    }
    {
      unsigned sufi = partial[tid];
      unsigned sufn = (tid + 1 < NTHREADS) ? partial[tid + 1] : 0u;
      if (sufi >= TOPK && sufn < TOPK) s_g = tid;
    }
    __syncthreads();
    if (tid == 0) {
      int g = s_g;
      unsigned acc = (g + 1 < NTHREADS) ? partial[g + 1] : 0u;
      int b = 2 * g;
      for (int q = 1; q >= 0; q--) {
        acc += hist[2 * g + q];
        if (acc >= TOPK) { b = 2 * g + q; break; }
      }
      s_bstar = b;
    }
    __syncthreads();
    const unsigned bstar = (unsigned)s_bstar;
    if (tid == 0) s_cnt = 0u;
    __syncthreads();
    for (int c = tid; c < NV4; c += NTHREADS) {
      float4 t = row4[c];
      int vb = c * 4;
      float xs4[4] = {t.x, t.y, t.z, t.w};
#pragma unroll
      for (int q = 0; q < 4; q++) {
        unsigned cur = hlookup(s_hash, (unsigned)(vb + q));
        unsigned o = orderable(adjust_logit(xs4[q], cur));
        if ((o >> 21) >= bstar) {
          unsigned p = atomicAdd(&s_cnt, 1u);
          if (p < CAP) bufA[p] = ((unsigned long long)o << 32) | (unsigned)(vb + q);
        }
      }
    }
    __syncthreads();
    if (tid == 0) { int m = (int)s_cnt; s_n = (m > CAP) ? CAP : m; }
    __syncthreads();
    n = s_n;
    if (tid < CAP) {
      unsigned long long e = (tid < n) ? bufA[tid] : 0ull;
      sort512(e, bufA, bufB, tid);
    }
    __syncthreads();
  }
  n = s_n;

  // ---- Decode + parallel exps ----
  if (tid < CAP) {
    unsigned long long kk = bufA[tid];
    if (tid < n) { sval[tid] = inv_orderable((unsigned)(kk >> 32)); sidx[tid] = (int)(kk & 0xFFFFFFFFu); }
    else         { sval[tid] = -INFINITY; sidx[tid] = 0x7FFFFFFF; }
  }
  __syncthreads();
  float m0 = sval[0];
  if (tid < CAP) se[tid] = (tid < n) ? expf(sval[tid] - m0) : 0.0f;
  __syncthreads();

  // ---- Serial epilogue (order-sensitive sums only) ----
  if (tid == 0) {
    const float T = (float)(1.0 - 0.9);
    float tau = sval[TOPK - 1];
    int Kp = n;
    for (int i = TOPK; i < n; i++) if (sval[i] < tau) { Kp = i; break; }
    float Ssum = 0.f;
    for (int i = Kp - 1; i >= 0; i--) Ssum += se[i];           // ascending value order
    float c = 0.f; int J = Kp;
    for (int i = Kp - 1; i >= 0; i--) {
      c += se[i] / Ssum;
      if (c > T) { J = i + 1; break; }
    }
    float Z = 0.f;
    for (int i = J - 1; i >= 0; i--) Z += se[i];
    s_J = J; s_Z = Z;
  }
  __syncthreads();
  int J = s_J;
  float Z = s_Z;

  if (prob_off >= 0) {
    float* prow = out + prob_off + (size_t)s * VOCAB;
    for (int i = tid; i < J; i += NTHREADS) prow[sidx[i]] = se[i] / Z;
  }

  // ---- Gumbel-argmax sampling over the J survivors (warp 0) ----
  if (tok_off >= 0 && tid < 32) {
    float best = -INFINITY; int bidx = 0x7FFFFFFF;
    for (int i = tid; i < J; i += 32) {
      float sc = logf(se[i] / Z) + gumbel_at((long long)s * VOCAB + sidx[i]);
      if (sc > best || (sc == best && sidx[i] < bidx)) { best = sc; bidx = sidx[i]; }
    }
    for (int o = 16; o; o >>= 1) {
      float ob = __shfl_down_sync(0xffffffffu, best, o);
      int oi   = __shfl_down_sync(0xffffffffu, bidx, o);
      if (ob > best || (ob == best && oi < bidx)) { best = ob; bidx = oi; }
    }
    if (tid == 0) {
      if (tok_int) ((int*)out)[tok_off + s] = bidx;
      else         out[tok_off + s] = (float)bidx;
    }
  }
}

extern "C" void kernel_launch(void* const* d_in, const int* in_sizes, int n_in,
                              void* d_out, int out_size) {
  const float* logits = (const float*)d_in[0];
  const int* prompt  = (const int*)d_in[1];
  const int* outtok  = (const int*)d_in[2];
  const int* eos     = (const int*)d_in[3];
  int np = in_sizes[1], no = in_sizes[2], ne = in_sizes[3];

  const long long SV = (long long)NSEQ * VOCAB;
  int prob_off, tok_off, tok_int;
  if (out_size == (int)(SV + NSEQ)) { tok_off = 0;  prob_off = NSEQ; tok_int = 0; }
  else if (out_size == (int)SV)     { tok_off = -1; prob_off = 0;    tok_int = 0; }
  else if (out_size == NSEQ)        { tok_off = 0;  prob_off = -1;   tok_int = 1; }
  else                              { tok_off = 0;  prob_off = NSEQ; tok_int = 0; }

  if (prob_off >= 0) {
    float4* pz = (float4*)((float*)d_out + prob_off);
    k_zero<<<2048, 256>>>(pz, (int)(SV / 4));   // pure-write stream
  }
  k_main<<<NSEQ, NTHREADS>>>(logits, prompt, np, outtok, no, eos, ne,
                             (float*)d_out, prob_off, tok_off, tok_int);
}

// round 13
// speedup vs baseline: 1.8130x; 1.8130x over previous
#include <cuda_runtime.h>
#include <math.h>
#include <stdint.h>

#define VOCAB    128000
#define NSEQ     256
#define TOPK     50
#define NTHREADS 1024
#define NBINS    2048          // slow path only (11-bit orderable)
#define CAP      512           // candidate capacity == sort size
#define NV4      (VOCAB / 4)
#define THX      2.85f         // raw-logit prefilter
#define THY      3.5625f       // = THX/0.8 : upper bound on y for filtered elements
#define HSIZE    4096
#define HMASK    4095
#define HEMPTY   0xFFFFFFFFu

// smem hash slot: [id:17][eos:1][prompt:1][cnt:13]
__device__ __forceinline__ void hinsert(unsigned* h, unsigned id, unsigned addv, unsigned orv) {
  unsigned slot = (id * 2654435761u) >> 20;
  unsigned tag = id << 15;
  for (;;) {
    unsigned cur = h[slot];
    if (cur == HEMPTY) {
      unsigned prev = atomicCAS(&h[slot], HEMPTY, tag);
      cur = (prev == HEMPTY) ? tag : prev;
    }
    if ((cur >> 15) == id) {
      if (orv)  atomicOr(&h[slot], orv);
      if (addv) atomicAdd(&h[slot], addv);
      return;
    }
    slot = (slot + 1) & HMASK;
  }
}
__device__ __forceinline__ unsigned hlookup(const unsigned* h, unsigned id) {
  unsigned slot = (id * 2654435761u) >> 20;
  for (;;) {
    unsigned cur = h[slot];
    if (cur == HEMPTY) return 0u;
    if ((cur >> 15) == id) return cur;
    slot = (slot + 1) & HMASK;
  }
}

// Bit-faithful to the reference float path: every op rounded separately (no FFMA).
__device__ __forceinline__ float adjust_logit(float x, unsigned cur) {
  if (cur & (1u << 14)) return -INFINITY;                  // eos mask
  unsigned cnt = cur & 0x1FFFu;
  bool penal = (cur & (1u << 13)) || (cnt != 0);           // prompt|output mask
  float rep = penal ? 1.1f : 1.0f;
  float y = (x > 0.0f) ? __fdiv_rn(x, rep) : __fmul_rn(x, rep);
  y = __fsub_rn(y, __fmul_rn(0.1f, (float)cnt));           // frequency
  if (cnt > 0) y = __fsub_rn(y, 0.2f);                     // presence
  y = __fdiv_rn(y, 0.8f);                                  // temperature
  return y;
}

__device__ __forceinline__ unsigned orderable(float f) {
  unsigned u = __float_as_uint(f);
  return (u & 0x80000000u) ? ~u : (u | 0x80000000u);
}
__device__ __forceinline__ float inv_orderable(unsigned o) {
  return __uint_as_float((o & 0x80000000u) ? (o ^ 0x80000000u) : ~o);
}

// JAX threefry2x32, partitionable: bits = x0 ^ x1 of threefry(key=(0,1), counter=(0, n))
__device__ __forceinline__ float gumbel_at(long long n) {
  unsigned c0 = (unsigned)((unsigned long long)n >> 32);
  unsigned c1 = (unsigned)n;
  const unsigned ks0 = 0u, ks1 = 1u, ks2 = 0x1BD11BDBu;
  unsigned x0 = c0 + ks0, x1 = c1 + ks1;
#define TF_RND(r) { x0 += x1; x1 = (x1 << (r)) | (x1 >> (32 - (r))); x1 ^= x0; }
  TF_RND(13) TF_RND(15) TF_RND(26) TF_RND(6)  x0 += ks1; x1 += ks2 + 1u;
  TF_RND(17) TF_RND(29) TF_RND(16) TF_RND(24) x0 += ks2; x1 += ks0 + 2u;
  TF_RND(13) TF_RND(15) TF_RND(26) TF_RND(6)  x0 += ks0; x1 += ks1 + 3u;
  TF_RND(17) TF_RND(29) TF_RND(16) TF_RND(24) x0 += ks1; x1 += ks2 + 4u;
  TF_RND(13) TF_RND(15) TF_RND(26) TF_RND(6)  x0 += ks2; x1 += ks0 + 5u;
#undef TF_RND
  unsigned bits = x0 ^ x1;
  float f = __uint_as_float((bits >> 9) | 0x3f800000u) - 1.0f;
  float u = fmaxf(__uint_as_float(0x00800000u), f);
  return -logf(-logf(u));
}

#define BAR512() asm volatile("bar.sync 1, 512;" ::: "memory")

// Descending bitonic sort of 512 u64 keys, one per thread (tid<512 call this).
__device__ __forceinline__ unsigned long long sort512(
    unsigned long long e, unsigned long long* bufA, unsigned long long* bufB, int tid) {
  int phase = 0;
#pragma unroll
  for (int k = 2; k <= 512; k <<= 1) {
#pragma unroll
    for (int j = k >> 1; j > 0; j >>= 1) {
      unsigned long long o;
      if (j < 32) {
        o = __shfl_xor_sync(0xffffffffu, e, j);
      } else {
        unsigned long long* buf = (phase & 1) ? bufB : bufA;
        buf[tid] = e;
        BAR512();
        o = buf[tid ^ j];
        phase ^= 1;
      }
      bool dirAsc = ((tid & k) != 0);       // final pass: all descending
      bool lower  = ((tid & j) == 0);
      bool takeMin = (dirAsc == lower);
      if (takeMin ? (o < e) : (o > e)) e = o;
    }
  }
  BAR512();
  bufA[tid] = e;
  return e;
}

__global__ __launch_bounds__(NTHREADS, 2)
void k_main(const float* __restrict__ logits,
            const int* __restrict__ prompt, int np,
            const int* __restrict__ outtok, int no,
            const int* __restrict__ eos, int ne,
            float* __restrict__ out,
            int prob_off, int tok_off, int tok_int) {
  __shared__ unsigned s_hash[HSIZE];                     // 16 KB
  __shared__ __align__(16) unsigned long long bufA[CAP]; // 4 KB
  __shared__ __align__(16) unsigned long long u64mem[1024]; // 8 KB union
  __shared__ float se[CAP];                              // 2 KB
  __shared__ unsigned partial[NTHREADS];                 // 4 KB (slow path)
  __shared__ unsigned s_cnt;
  __shared__ int s_g, s_bstar, s_J, s_ok, s_n;
  __shared__ float s_Z;

  unsigned long long* bufB = u64mem;
  float* sval = (float*)(u64mem + 512);
  int*   sidx = (int*)((char*)(u64mem + 512) + 2048);
  unsigned* hist = (unsigned*)u64mem;

  const int s = blockIdx.x;
  const int tid = threadIdx.x;

  if (tid == 0) { s_cnt = 0u; s_g = 0; }
  __syncthreads();

  const float4* row4 = (const float4*)(logits + (size_t)s * VOCAB);
  float4* prow4 = (prob_off >= 0) ? (float4*)(out + prob_off + (size_t)s * VOCAB) : (float4*)0;
  const float4 zero4 = make_float4(0.f, 0.f, 0.f, 0.f);

  // ---- Fused duplex stream (proven-best config): zero-fill + RAW candidate collect.
  //      No hash work in this loop — penalties are applied post-stream to ~600 survivors.
#pragma unroll 4
  for (int c = tid; c < NV4; c += NTHREADS) {
    float4 t = __ldcs(&row4[c]);
    if (prow4) __stcs(&prow4[c], zero4);
    float mx = fmaxf(fmaxf(t.x, t.y), fmaxf(t.z, t.w));
    if (mx > THX) {
      int vb = c * 4;
      float xs4[4] = {t.x, t.y, t.z, t.w};
#pragma unroll
      for (int q = 0; q < 4; q++) {
        if (xs4[q] > THX) {
          unsigned p = atomicAdd(&s_cnt, 1u);
          if (p < CAP) bufA[p] = ((unsigned long long)orderable(xs4[q]) << 32) | (unsigned)(vb + q);
        }
      }
    }
  }
  __syncthreads();

  // ---- Penalty hash build (off the stream's critical path) ----
  for (int i = tid; i < HSIZE; i += NTHREADS) s_hash[i] = HEMPTY;
  __syncthreads();
  for (int i = tid; i < np; i += NTHREADS) hinsert(s_hash, (unsigned)prompt[i], 0u, 1u << 13);
  for (int i = tid; i < no; i += NTHREADS) hinsert(s_hash, (unsigned)outtok[i], 1u, 0u);
  for (int i = tid; i < ne; i += NTHREADS) hinsert(s_hash, (unsigned)eos[i], 0u, 1u << 14);
  __syncthreads();

  int n = (int)s_cnt;
  bool okn = (n >= TOPK && n <= CAP);
  if (okn) {
    // Apply penalties to candidates only, re-key by adjusted value y.
    if (tid < CAP) {
      unsigned long long e;
      if (tid < n) {
        unsigned long long kk = bufA[tid];
        float x = inv_orderable((unsigned)(kk >> 32));
        unsigned id = (unsigned)(kk & 0xFFFFFFFFu);
        float y = adjust_logit(x, hlookup(s_hash, id));
        e = ((unsigned long long)orderable(y) << 32) | id;
      } else {
        e = 0ull;
      }
      BAR512();
      sort512(e, bufA, bufB, tid);
    }
    __syncthreads();
    if (tid == 0) {
      float v50 = inv_orderable((unsigned)(bufA[TOPK - 1] >> 32));
      s_ok = (v50 > THY) ? 1 : 0;     // candidate set provably covers top-k + ties
      s_n = n;
    }
  } else {
    if (tid == 0) s_ok = 0;
  }
  __syncthreads();

  // ---- Guarded slow path (histogram select over full vocab; bit-identical math) ----
  if (!s_ok) {
    for (int i = tid; i < NBINS; i += NTHREADS) hist[i] = 0u;
    if (tid == 0) s_cnt = 0u;
    __syncthreads();
    for (int c = tid; c < NV4; c += NTHREADS) {
      float4 t = row4[c];
      int vb = c * 4;
      float xs4[4] = {t.x, t.y, t.z, t.w};
#pragma unroll
    for (int q = 0; q < 4; q++) {
        unsigned cur = hlookup(s_hash, (unsigned)(vb + q));
        atomicAdd(&hist[orderable(adjust_logit(xs4[q], cur)) >> 21], 1u);
      }
    }
    __syncthreads();
    unsigned ps = hist[2 * tid] + hist[2 * tid + 1];
    partial[tid] = ps;
    __syncthreads();
    for (int off = 1; off < NTHREADS; off <<= 1) {
      unsigned a = (tid + off < NTHREADS) ? partial[tid + off] : 0u;
      __syncthreads();
      partial[tid] += a;
      __syncthreads();
    }
    {
      unsigned sufi = partial[tid];
      unsigned sufn = (tid + 1 < NTHREADS) ? partial[tid + 1] : 0u;
      if (sufi >= TOPK && sufn < TOPK) s_g = tid;
    }
    __syncthreads();
    if (tid == 0) {
      int g = s_g;
      unsigned acc = (g + 1 < NTHREADS) ? partial[g + 1] : 0u;
      int b = 2 * g;
      for (int q = 1; q >= 0; q--) {
        acc += hist[2 * g + q];
        if (acc >= TOPK) { b = 2 * g + q; break; }
      }
      s_bstar = b;
    }
    __syncthreads();
    const unsigned bstar = (unsigned)s_bstar;
    if (tid == 0) s_cnt = 0u;
    __syncthreads();
    for (int c = tid; c < NV4; c += NTHREADS) {
      float4 t = row4[c];
      int vb = c * 4;
      float xs4[4] = {t.x, t.y, t.z, t.w};
#pragma unroll
      for (int q = 0; q < 4; q++) {
        unsigned cur = hlookup(s_hash, (unsigned)(vb + q));
        unsigned o = orderable(adjust_logit(xs4[q], cur));
        if ((o >> 21) >= bstar) {
          unsigned p = atomicAdd(&s_cnt, 1u);
          if (p < CAP) bufA[p] = ((unsigned long long)o << 32) | (unsigned)(vb + q);
        }
      }
    }
    __syncthreads();
    if (tid == 0) { int m = (int)s_cnt; s_n = (m > CAP) ? CAP : m; }
    __syncthreads();
    n = s_n;
    if (tid < CAP) {
      unsigned long long e = (tid < n) ? bufA[tid] : 0ull;
      sort512(e, bufA, bufB, tid);
    }
    __syncthreads();
  }
  n = s_n;

  // ---- Decode + parallel exps ----
  if (tid < CAP) {
    unsigned long long kk = bufA[tid];
    if (tid < n) { sval[tid] = inv_orderable((unsigned)(kk >> 32)); sidx[tid] = (int)(kk & 0xFFFFFFFFu); }
    else         { sval[tid] = -INFINITY; sidx[tid] = 0x7FFFFFFF; }
  }
  __syncthreads();
  float m0 = sval[0];
  if (tid < CAP) se[tid] = (tid < n) ? expf(sval[tid] - m0) : 0.0f;
  __syncthreads();

  // ---- Serial epilogue (order-sensitive sums only) ----
  if (tid == 0) {
    const float T = (float)(1.0 - 0.9);
    float tau = sval[TOPK - 1];
    int Kp = n;
    for (int i = TOPK; i < n; i++) if (sval[i] < tau) { Kp = i; break; }
    float Ssum = 0.f;
    for (int i = Kp - 1; i >= 0; i--) Ssum += se[i];           // ascending value order
    float c = 0.f; int J = Kp;
    for (int i = Kp - 1; i >= 0; i--) {
      c += se[i] / Ssum;
      if (c > T) { J = i + 1; break; }
    }
    float Z = 0.f;
    for (int i = J - 1; i >= 0; i--) Z += se[i];
    s_J = J; s_Z = Z;
  }
  __syncthreads();
  int J = s_J;
  float Z = s_Z;

  if (prob_off >= 0) {
    float* prow = out + prob_off + (size_t)s * VOCAB;
    for (int i = tid; i < J; i += NTHREADS) prow[sidx[i]] = se[i] / Z;
  }

  // ---- Gumbel-argmax sampling over the J survivors (warp 0) ----
  if (tok_off >= 0 && tid < 32) {
    float best = -INFINITY; int bidx = 0x7FFFFFFF;
    for (int i = tid; i < J; i += 32) {
      float sc = logf(se[i] / Z) + gumbel_at((long long)s * VOCAB + sidx[i]);
      if (sc > best || (sc == best && sidx[i] < bidx)) { best = sc; bidx = sidx[i]; }
    }
    for (int o = 16; o; o >>= 1) {
      float ob = __shfl_down_sync(0xffffffffu, best, o);
      int oi   = __shfl_down_sync(0xffffffffu, bidx, o);
      if (ob > best || (ob == best && oi < bidx)) { best = ob; bidx = oi; }
    }
    if (tid == 0) {
      if (tok_int) ((int*)out)[tok_off + s] = bidx;
      else         out[tok_off + s] = (float)bidx;
    }
  }
}

extern "C" void kernel_launch(void* const* d_in, const int* in_sizes, int n_in,
                              void* d_out, int out_size) {
  const float* logits = (const float*)d_in[0];
  const int* prompt  = (const int*)d_in[1];
  const int* outtok  = (const int*)d_in[2];
  const int* eos     = (const int*)d_in[3];
  int np = in_sizes[1], no = in_sizes[2], ne = in_sizes[3];

  const long long SV = (long long)NSEQ * VOCAB;
  int prob_off, tok_off, tok_int;
  if (out_size == (int)(SV + NSEQ)) { tok_off = 0;  prob_off = NSEQ; tok_int = 0; }
  else if (out_size == (int)SV)     { tok_off = -1; prob_off = 0;    tok_int = 0; }
  else if (out_size == NSEQ)        { tok_off = 0;  prob_off = -1;   tok_int = 1; }
  else                              { tok_off = 0;  prob_off = NSEQ; tok_int = 0; }

  k_main<<<NSEQ, NTHREADS>>>(logits, prompt, np, outtok, no, eos, ne,
                             (float*)d_out, prob_off, tok_off, tok_int);
}

// round 14
// speedup vs baseline: 1.8140x; 1.0006x over previous
#include <cuda_runtime.h>
#include <math.h>
#include <stdint.h>

#define VOCAB    128000
#define NSEQ     256
#define TOPK     50
#define NTHREADS 1024
#define NSTREAM  896           // warps 0-27 stream; warps 28-31 build the hash
#define NBINS    2048          // slow path only (11-bit orderable)
#define CAP      512           // candidate capacity == sort size
#define NV4      (VOCAB / 4)
#define THX      2.85f         // raw-logit prefilter
#define THY      3.5625f       // = THX/0.8 : upper bound on y for filtered elements
#define HSIZE    4096
#define HMASK    4095
#define HEMPTY   0xFFFFFFFFu

// smem hash slot: [id:17][eos:1][prompt:1][cnt:13]
__device__ __forceinline__ void hinsert(unsigned* h, unsigned id, unsigned addv, unsigned orv) {
  unsigned slot = (id * 2654435761u) >> 20;
  unsigned tag = id << 15;
  for (;;) {
    unsigned cur = h[slot];
    if (cur == HEMPTY) {
      unsigned prev = atomicCAS(&h[slot], HEMPTY, tag);
      cur = (prev == HEMPTY) ? tag : prev;
    }
    if ((cur >> 15) == id) {
      if (orv)  atomicOr(&h[slot], orv);
      if (addv) atomicAdd(&h[slot], addv);
      return;
    }
    slot = (slot + 1) & HMASK;
  }
}
__device__ __forceinline__ unsigned hlookup(const unsigned* h, unsigned id) {
  unsigned slot = (id * 2654435761u) >> 20;
  for (;;) {
    unsigned cur = h[slot];
    if (cur == HEMPTY) return 0u;
    if ((cur >> 15) == id) return cur;
    slot = (slot + 1) & HMASK;
  }
}

// Bit-faithful to the reference float path: every op rounded separately (no FFMA).
__device__ __forceinline__ float adjust_logit(float x, unsigned cur) {
  if (cur & (1u << 14)) return -INFINITY;                  // eos mask
  unsigned cnt = cur & 0x1FFFu;
  bool penal = (cur & (1u << 13)) || (cnt != 0);           // prompt|output mask
  float rep = penal ? 1.1f : 1.0f;
  float y = (x > 0.0f) ? __fdiv_rn(x, rep) : __fmul_rn(x, rep);
  y = __fsub_rn(y, __fmul_rn(0.1f, (float)cnt));           // frequency
  if (cnt > 0) y = __fsub_rn(y, 0.2f);                     // presence
  y = __fdiv_rn(y, 0.8f);                                  // temperature
  return y;
}

__device__ __forceinline__ unsigned orderable(float f) {
  unsigned u = __float_as_uint(f);
  return (u & 0x80000000u) ? ~u : (u | 0x80000000u);
}
__device__ __forceinline__ float inv_orderable(unsigned o) {
  return __uint_as_float((o & 0x80000000u) ? (o ^ 0x80000000u) : ~o);
}

// JAX threefry2x32, partitionable: bits = x0 ^ x1 of threefry(key=(0,1), counter=(0, n))
__device__ __forceinline__ float gumbel_at(long long n) {
  unsigned c0 = (unsigned)((unsigned long long)n >> 32);
  unsigned c1 = (unsigned)n;
  const unsigned ks0 = 0u, ks1 = 1u, ks2 = 0x1BD11BDBu;
  unsigned x0 = c0 + ks0, x1 = c1 + ks1;
#define TF_RND(r) { x0 += x1; x1 = (x1 << (r)) | (x1 >> (32 - (r))); x1 ^= x0; }
  TF_RND(13) TF_RND(15) TF_RND(26) TF_RND(6)  x0 += ks1; x1 += ks2 + 1u;
  TF_RND(17) TF_RND(29) TF_RND(16) TF_RND(24) x0 += ks2; x1 += ks0 + 2u;
  TF_RND(13) TF_RND(15) TF_RND(26) TF_RND(6)  x0 += ks0; x1 += ks1 + 3u;
  TF_RND(17) TF_RND(29) TF_RND(16) TF_RND(24) x0 += ks1; x1 += ks2 + 4u;
  TF_RND(13) TF_RND(15) TF_RND(26) TF_RND(6)  x0 += ks2; x1 += ks0 + 5u;
#undef TF_RND
  unsigned bits = x0 ^ x1;
  float f = __uint_as_float((bits >> 9) | 0x3f800000u) - 1.0f;
  float u = fmaxf(__uint_as_float(0x00800000u), f);
  return -logf(-logf(u));
}

#define BAR512() asm volatile("bar.sync 1, 512;" ::: "memory")

// Descending bitonic sort of 512 u64 keys, one per thread (tid<512 call this).
__device__ __forceinline__ unsigned long long sort512(
    unsigned long long e, unsigned long long* bufA, unsigned long long* bufB, int tid) {
  int phase = 0;
#pragma unroll
  for (int k = 2; k <= 512; k <<= 1) {
#pragma unroll
    for (int j = k >> 1; j > 0; j >>= 1) {
      unsigned long long o;
      if (j < 32) {
        o = __shfl_xor_sync(0xffffffffu, e, j);
      } else {
        unsigned long long* buf = (phase & 1) ? bufB : bufA;
        buf[tid] = e;
        BAR512();
        o = buf[tid ^ j];
        phase ^= 1;
      }
      bool dirAsc = ((tid & k) != 0);       // final pass: all descending
      bool lower  = ((tid & j) == 0);
      bool takeMin = (dirAsc == lower);
      if (takeMin ? (o < e) : (o > e)) e = o;
    }
  }
  BAR512();
  bufA[tid] = e;
  return e;
}

__global__ __launch_bounds__(NTHREADS, 2)
void k_main(const float* __restrict__ logits,
            const int* __restrict__ prompt, int np,
            const int* __restrict__ outtok, int no,
            const int* __restrict__ eos, int ne,
            float* __restrict__ out,
            int prob_off, int tok_off, int tok_int) {
  __shared__ unsigned s_hash[HSIZE];                     // 16 KB
  __shared__ __align__(16) unsigned long long bufA[CAP]; // 4 KB
  __shared__ __align__(16) unsigned long long u64mem[1024]; // 8 KB union
  __shared__ float se[CAP];                              // 2 KB
  __shared__ unsigned partial[NTHREADS];                 // 4 KB (slow path)
  __shared__ unsigned s_cnt;
  __shared__ int s_g, s_bstar, s_J, s_ok, s_n;
  __shared__ float s_Z;

  unsigned long long* bufB = u64mem;
  float* sval = (float*)(u64mem + 512);
  int*   sidx = (int*)((char*)(u64mem + 512) + 2048);
  unsigned* hist = (unsigned*)u64mem;

  const int s = blockIdx.x;
  const int tid = threadIdx.x;

  if (tid == 0) { s_cnt = 0u; s_g = 0; }
  __syncthreads();

  const float4* row4 = (const float4*)(logits + (size_t)s * VOCAB);
  float4* prow4 = (prob_off >= 0) ? (float4*)(out + prob_off + (size_t)s * VOCAB) : (float4*)0;
  const float4 zero4 = make_float4(0.f, 0.f, 0.f, 0.f);

  // ---- Warp specialization: warps 0-27 run the duplex stream; warps 28-31
  //      concurrently build the penalty hash (needed only after the stream).
  if (tid < NSTREAM) {
#pragma unroll 4
    for (int c = tid; c < NV4; c += NSTREAM) {
      float4 t = __ldcs(&row4[c]);
      if (prow4) __stcs(&prow4[c], zero4);
      float mx = fmaxf(fmaxf(t.x, t.y), fmaxf(t.z, t.w));
      if (mx > THX) {
        int vb = c * 4;
        float xs4[4] = {t.x, t.y, t.z, t.w};
#pragma unroll
        for (int q = 0; q < 4; q++) {
          if (xs4[q] > THX) {
            unsigned p = atomicAdd(&s_cnt, 1u);
            if (p < CAP) bufA[p] = ((unsigned long long)orderable(xs4[q]) << 32) | (unsigned)(vb + q);
          }
        }
      }
    }
  } else {
    const int hid = tid - NSTREAM;           // 0..127
    for (int i = hid; i < HSIZE; i += 128) s_hash[i] = HEMPTY;
    asm volatile("bar.sync 2, 128;" ::: "memory");   // hash zeroed before inserts
    for (int i = hid; i < np; i += 128) hinsert(s_hash, (unsigned)prompt[i], 0u, 1u << 13);
    for (int i = hid; i < no; i += 128) hinsert(s_hash, (unsigned)outtok[i], 1u, 0u);
    for (int i = hid; i < ne; i += 128) hinsert(s_hash, (unsigned)eos[i], 0u, 1u << 14);
  }
  __syncthreads();

  int n = (int)s_cnt;
  bool okn = (n >= TOPK && n <= CAP);
  if (okn) {
    // Apply penalties to candidates only, re-key by adjusted value y.
    if (tid < CAP) {
      unsigned long long e;
      if (tid < n) {
        unsigned long long kk = bufA[tid];
        float x = inv_orderable((unsigned)(kk >> 32));
        unsigned id = (unsigned)(kk & 0xFFFFFFFFu);
        float y = adjust_logit(x, hlookup(s_hash, id));
        e = ((unsigned long long)orderable(y) << 32) | id;
      } else {
        e = 0ull;
      }
      BAR512();
      sort512(e, bufA, bufB, tid);
    }
    __syncthreads();
    if (tid == 0) {
      float v50 = inv_orderable((unsigned)(bufA[TOPK - 1] >> 32));
      s_ok = (v50 > THY) ? 1 : 0;     // candidate set provably covers top-k + ties
      s_n = n;
    }
  } else {
    if (tid == 0) s_ok = 0;
  }
  __syncthreads();

  // ---- Guarded slow path (histogram select over full vocab; bit-identical math) ----
  if (!s_ok) {
    for (int i = tid; i < NBINS; i += NTHREADS) hist[i] = 0u;
    if (tid == 0) s_cnt = 0u;
    __syncthreads();
    for (int c = tid; c < NV4; c += NTHREADS) {
      float4 t = row4[c];
      int vb = c * 4;
      float xs4[4] = {t.x, t.y, t.z, t.w};
#pragma unroll
      for (int q = 0; q < 4; q++) {
        unsigned cur = hlookup(s_hash, (unsigned)(vb + q));
        atomicAdd(&hist[orderable(adjust_logit(xs4[q], cur)) >> 21], 1u);
      }
    }
    __syncthreads();
    unsigned ps = hist[2 * tid] + hist[2 * tid + 1];
    partial[tid] = ps;
    __syncthreads();
    for (int off = 1; off < NTHREADS; off <<= 1) {
      unsigned a = (tid + off < NTHREADS) ? partial[tid + off] : 0u;
      __syncthreads();
      partial[tid] += a;
      __syncthreads();
    }
    {
      unsigned sufi = partial[tid];
      unsigned sufn = (tid + 1 < NTHREADS) ? partial[tid + 1] : 0u;
      if (sufi >= TOPK && sufn < TOPK) s_g = tid;
    }
    __syncthreads();
    if (tid == 0) {
      int g = s_g;
      unsigned acc = (g + 1 < NTHREADS) ? partial[g + 1] : 0u;
      int b = 2 * g;
      for (int q = 1; q >= 0; q--) {
        acc += hist[2 * g + q];
        if (acc >= TOPK) { b = 2 * g + q; break; }
      }
      s_bstar = b;
    }
    __syncthreads();
    const unsigned bstar = (unsigned)s_bstar;
    if (tid == 0) s_cnt = 0u;
    __syncthreads();
    for (int c = tid; c < NV4; c += NTHREADS) {
      float4 t = row4[c];
      int vb = c * 4;
      float xs4[4] = {t.x, t.y, t.z, t.w};
#pragma unroll
      for (int q = 0; q < 4; q++) {
        unsigned cur = hlookup(s_hash, (unsigned)(vb + q));
        unsigned o = orderable(adjust_logit(xs4[q], cur));
        if ((o >> 21) >= bstar) {
          unsigned p = atomicAdd(&s_cnt, 1u);
          if (p < CAP) bufA[p] = ((unsigned long long)o << 32) | (unsigned)(vb + q);
        }
      }
    }
    __syncthreads();
    if (tid == 0) { int m = (int)s_cnt; s_n = (m > CAP) ? CAP : m; }
    __syncthreads();
    n = s_n;
    if (tid < CAP) {
      unsigned long long e = (tid < n) ? bufA[tid] : 0ull;
      sort512(e, bufA, bufB, tid);
    }
    __syncthreads();
  }
  n = s_n;

  // ---- Decode + parallel exps ----
  if (tid < CAP) {
    unsigned long long kk = bufA[tid];
    if (tid < n) { sval[tid] = inv_orderable((unsigned)(kk >> 32)); sidx[tid] = (int)(kk & 0xFFFFFFFFu); }
    else         { sval[tid] = -INFINITY; sidx[tid] = 0x7FFFFFFF; }
  }
  __syncthreads();
  float m0 = sval[0];
  if (tid < CAP) se[tid] = (tid < n) ? expf(sval[tid] - m0) : 0.0f;
  __syncthreads();

  // ---- Serial epilogue (order-sensitive sums only) ----
  if (tid == 0) {
    const float T = (float)(1.0 - 0.9);
    float tau = sval[TOPK - 1];
    int Kp = n;
    for (int i = TOPK; i < n; i++) if (sval[i] < tau) { Kp = i; break; }
    float Ssum = 0.f;
    for (int i = Kp - 1; i >= 0; i--) Ssum += se[i];           // ascending value order
    float c = 0.f; int J = Kp;
    for (int i = Kp - 1; i >= 0; i--) {
      c += se[i] / Ssum;
      if (c > T) { J = i + 1; break; }
    }
    float Z = 0.f;
    for (int i = J - 1; i >= 0; i--) Z += se[i];
    s_J = J; s_Z = Z;
  }
  __syncthreads();
  int J = s_J;
  float Z = s_Z;

  if (prob_off >= 0) {
    float* prow = out + prob_off + (size_t)s * VOCAB;
    for (int i = tid; i < J; i += NTHREADS) prow[sidx[i]] = se[i] / Z;
  }

  // ---- Gumbel-argmax sampling over the J survivors (warp 0) ----
  if (tok_off >= 0 && tid < 32) {
    float best = -INFINITY; int bidx = 0x7FFFFFFF;
    for (int i = tid; i < J; i += 32) {
      float sc = logf(se[i] / Z) + gumbel_at((long long)s * VOCAB + sidx[i]);
      if (sc > best || (sc == best && sidx[i] < bidx)) { best = sc; bidx = sidx[i]; }
    }
    for (int o = 16; o; o >>= 1) {
      float ob = __shfl_down_sync(0xffffffffu, best, o);
      int oi   = __shfl_down_sync(0xffffffffu, bidx, o);
      if (ob > best || (ob == best && oi < bidx)) { best = ob; bidx = oi; }
    }
    if (tid == 0) {
      if (tok_int) ((int*)out)[tok_off + s] = bidx;
      else         out[tok_off + s] = (float)bidx;
    }
  }
}

extern "C" void kernel_launch(void* const* d_in, const int* in_sizes, int n_in,
                              void* d_out, int out_size) {
  const float* logits = (const float*)d_in[0];
  const int* prompt  = (const int*)d_in[1];
  const int* outtok  = (const int*)d_in[2];
  const int* eos     = (const int*)d_in[3];
  int np = in_sizes[1], no = in_sizes[2], ne = in_sizes[3];

  const long long SV = (long long)NSEQ * VOCAB;
  int prob_off, tok_off, tok_int;
  if (out_size == (int)(SV + NSEQ)) { tok_off = 0;  prob_off = NSEQ; tok_int = 0; }
  else if (out_size == (int)SV)     { tok_off = -1; prob_off = 0;    tok_int = 0; }
  else if (out_size == NSEQ)        { tok_off = 0;  prob_off = -1;   tok_int = 1; }
  else                              { tok_off = 0;  prob_off = NSEQ; tok_int = 0; }

  k_main<<<NSEQ, NTHREADS>>>(logits, prompt, np, outtok, no, eos, ne,
                             (float*)d_out, prob_off, tok_off, tok_int);
}